// round 2
// baseline (speedup 1.0000x reference)
#include <cuda_runtime.h>
#include <cuda_bf16.h>

// ---------------------------------------------------------------------------
// GlobalIntrinsicLinear: y = x @ (W0 + Fastfood(theta))^T + b
//   Fastfood: v = H(B*theta_pad); v = v[Pi]*G; v = H(v); update = v[:DD]/sqrt(sum(G^2)*DD)
//   H is unnormalized FWHT over 2^20 = H_1024 (x) H_1024  (row pass + column pass)
// ---------------------------------------------------------------------------

#define LL   (1 << 20)
#define DD   (1024 * 768)
#define OUTF 1024
#define INF  768
#define MTOT 16384            // 8 * 2048

// Scratch (no cudaMalloc allowed)
__device__ float g_v[LL];
__device__ float g_u[LL];
__device__ float g_W[DD];
__device__ float g_part[1024];
__device__ float g_scale;

// ---------------------------------------------------------------------------
// Step 0: v = BB * theta_pad
// ---------------------------------------------------------------------------
__global__ void k_init(const float* __restrict__ theta, const float* __restrict__ BB,
                       int ntheta) {
    int i = blockIdx.x * blockDim.x + threadIdx.x;
    if (i < LL) {
        float t = (i < ntheta) ? theta[i] : 0.0f;
        g_v[i] = BB[i] * t;
    }
}

// ---------------------------------------------------------------------------
// FWHT over length-1024 rows (low 10 index bits) of a 1024x1024 view
// ---------------------------------------------------------------------------
__global__ void k_fwht_rows(float* __restrict__ v) {
    __shared__ float s[1024];
    float* p = v + (size_t)blockIdx.x * 1024;
    for (int i = threadIdx.x; i < 1024; i += 256) s[i] = p[i];
    __syncthreads();
#pragma unroll
    for (int h = 1; h < 1024; h <<= 1) {
        for (int idx = threadIdx.x; idx < 512; idx += 256) {
            int j = ((idx & ~(h - 1)) << 1) | (idx & (h - 1));
            float a = s[j], b = s[j + h];
            s[j] = a + b;
            s[j + h] = a - b;
        }
        __syncthreads();
    }
    for (int i = threadIdx.x; i < 1024; i += 256) p[i] = s[i];
}

// FWHT over length-1024 columns (high 10 index bits)
__global__ void k_fwht_cols(float* __restrict__ v) {
    __shared__ float s[1024];
    int col = blockIdx.x;
    for (int i = threadIdx.x; i < 1024; i += 256) s[i] = v[(size_t)i * 1024 + col];
    __syncthreads();
#pragma unroll
    for (int h = 1; h < 1024; h <<= 1) {
        for (int idx = threadIdx.x; idx < 512; idx += 256) {
            int j = ((idx & ~(h - 1)) << 1) | (idx & (h - 1));
            float a = s[j], b = s[j + h];
            s[j] = a + b;
            s[j + h] = a - b;
        }
        __syncthreads();
    }
    for (int i = threadIdx.x; i < 1024; i += 256) v[(size_t)i * 1024 + col] = s[i];
}

// ---------------------------------------------------------------------------
// u[i] = v[Pi[i]] * GG[i]       (Pi is int32 — JAX x64 is disabled)
// ---------------------------------------------------------------------------
__global__ void k_gather(const int* __restrict__ Pi, const float* __restrict__ GG) {
    int i = blockIdx.x * blockDim.x + threadIdx.x;
    if (i < LL) {
        int idx = Pi[i] & (LL - 1);   // clamp defensively, perm values < LL
        g_u[i] = g_v[idx] * GG[i];
    }
}

// ---------------------------------------------------------------------------
// Deterministic two-stage reduction of sum(GG^2)
// ---------------------------------------------------------------------------
__global__ void k_reduce1(const float* __restrict__ GG) {
    __shared__ float sm[256];
    int base = blockIdx.x * 1024;
    float s = 0.0f;
    for (int i = threadIdx.x; i < 1024; i += 256) {
        float g = GG[base + i];
        s += g * g;
    }
    sm[threadIdx.x] = s;
    __syncthreads();
    for (int st = 128; st > 0; st >>= 1) {
        if (threadIdx.x < st) sm[threadIdx.x] += sm[threadIdx.x + st];
        __syncthreads();
    }
    if (threadIdx.x == 0) g_part[blockIdx.x] = sm[0];
}

__global__ void k_reduce2() {
    __shared__ float sm[256];
    float s = 0.0f;
    for (int i = threadIdx.x; i < 1024; i += 256) s += g_part[i];
    sm[threadIdx.x] = s;
    __syncthreads();
    for (int st = 128; st > 0; st >>= 1) {
        if (threadIdx.x < st) sm[threadIdx.x] += sm[threadIdx.x + st];
        __syncthreads();
    }
    if (threadIdx.x == 0) {
        // 1 / (sqrt(LL*S) * sqrt(DD/LL)) == 1 / sqrt(S * DD)
        g_scale = 1.0f / sqrtf(sm[0] * (float)DD);
    }
}

// ---------------------------------------------------------------------------
// W_eff[i] = W0[i] + u[i] * scale
// ---------------------------------------------------------------------------
__global__ void k_makeW(const float* __restrict__ W0) {
    int i = blockIdx.x * blockDim.x + threadIdx.x;
    if (i < DD) {
        g_W[i] = W0[i] + g_u[i] * g_scale;
    }
}

// ---------------------------------------------------------------------------
// GEMM: Y[m,n] = sum_k X[m,k] * W[n,k] + bias[n]
// M=16384, N=1024, K=768. BM=BN=128, BK=16, 256 threads, 8x8 per thread.
// ---------------------------------------------------------------------------
__global__ __launch_bounds__(256, 2) void k_gemm(const float* __restrict__ X,
                                                 const float* __restrict__ bias,
                                                 float* __restrict__ Y) {
    __shared__ float As[2][16][128];
    __shared__ float Bs[2][16][128];

    const int tid = threadIdx.x;
    const int nBase = blockIdx.x * 128;
    const int mBase = blockIdx.y * 128;
    const int tx = tid & 15;       // n-direction, 8 cols each
    const int ty = tid >> 4;       // m-direction, 8 rows each

    const int lrow = tid >> 2;           // 0..63
    const int lc4 = (tid & 3) * 4;       // 0,4,8,12

    const float* Aptr = X + (size_t)(mBase + lrow) * INF + lc4;
    const float* Bptr = g_W + (size_t)(nBase + lrow) * INF + lc4;

    float4 ra0, ra1, rb0, rb1;

    float acc[8][8];
#pragma unroll
    for (int i = 0; i < 8; i++)
#pragma unroll
        for (int j = 0; j < 8; j++) acc[i][j] = 0.0f;

    // prologue: load tile 0
    ra0 = *(const float4*)(Aptr);
    ra1 = *(const float4*)(Aptr + 64 * INF);
    rb0 = *(const float4*)(Bptr);
    rb1 = *(const float4*)(Bptr + 64 * INF);
    {
        As[0][lc4 + 0][lrow] = ra0.x; As[0][lc4 + 1][lrow] = ra0.y;
        As[0][lc4 + 2][lrow] = ra0.z; As[0][lc4 + 3][lrow] = ra0.w;
        As[0][lc4 + 0][lrow + 64] = ra1.x; As[0][lc4 + 1][lrow + 64] = ra1.y;
        As[0][lc4 + 2][lrow + 64] = ra1.z; As[0][lc4 + 3][lrow + 64] = ra1.w;
        Bs[0][lc4 + 0][lrow] = rb0.x; Bs[0][lc4 + 1][lrow] = rb0.y;
        Bs[0][lc4 + 2][lrow] = rb0.z; Bs[0][lc4 + 3][lrow] = rb0.w;
        Bs[0][lc4 + 0][lrow + 64] = rb1.x; Bs[0][lc4 + 1][lrow + 64] = rb1.y;
        Bs[0][lc4 + 2][lrow + 64] = rb1.z; Bs[0][lc4 + 3][lrow + 64] = rb1.w;
    }
    __syncthreads();

    const int NT = INF / 16;   // 48
    for (int t = 0; t < NT; t++) {
        const int cur = t & 1;
        if (t + 1 < NT) {
            const int k0 = (t + 1) * 16;
            ra0 = *(const float4*)(Aptr + k0);
            ra1 = *(const float4*)(Aptr + 64 * INF + k0);
            rb0 = *(const float4*)(Bptr + k0);
            rb1 = *(const float4*)(Bptr + 64 * INF + k0);
        }
#pragma unroll
        for (int k = 0; k < 16; k++) {
            float a[8], bb[8];
            *(float4*)&a[0] = *(const float4*)&As[cur][k][ty * 8];
            *(float4*)&a[4] = *(const float4*)&As[cur][k][ty * 8 + 4];
            *(float4*)&bb[0] = *(const float4*)&Bs[cur][k][tx * 8];
            *(float4*)&bb[4] = *(const float4*)&Bs[cur][k][tx * 8 + 4];
#pragma unroll
            for (int i = 0; i < 8; i++)
#pragma unroll
                for (int j = 0; j < 8; j++)
                    acc[i][j] = fmaf(a[i], bb[j], acc[i][j]);
        }
        if (t + 1 < NT) {
            const int nxt = cur ^ 1;
            As[nxt][lc4 + 0][lrow] = ra0.x; As[nxt][lc4 + 1][lrow] = ra0.y;
            As[nxt][lc4 + 2][lrow] = ra0.z; As[nxt][lc4 + 3][lrow] = ra0.w;
            As[nxt][lc4 + 0][lrow + 64] = ra1.x; As[nxt][lc4 + 1][lrow + 64] = ra1.y;
            As[nxt][lc4 + 2][lrow + 64] = ra1.z; As[nxt][lc4 + 3][lrow + 64] = ra1.w;
            Bs[nxt][lc4 + 0][lrow] = rb0.x; Bs[nxt][lc4 + 1][lrow] = rb0.y;
            Bs[nxt][lc4 + 2][lrow] = rb0.z; Bs[nxt][lc4 + 3][lrow] = rb0.w;
            Bs[nxt][lc4 + 0][lrow + 64] = rb1.x; Bs[nxt][lc4 + 1][lrow + 64] = rb1.y;
            Bs[nxt][lc4 + 2][lrow + 64] = rb1.z; Bs[nxt][lc4 + 3][lrow + 64] = rb1.w;
        }
        __syncthreads();
    }

    // epilogue with bias
    float4 bv0 = *(const float4*)(bias + nBase + tx * 8);
    float4 bv1 = *(const float4*)(bias + nBase + tx * 8 + 4);
#pragma unroll
    for (int i = 0; i < 8; i++) {
        float* yp = Y + (size_t)(mBase + ty * 8 + i) * OUTF + nBase + tx * 8;
        float4 o0, o1;
        o0.x = acc[i][0] + bv0.x; o0.y = acc[i][1] + bv0.y;
        o0.z = acc[i][2] + bv0.z; o0.w = acc[i][3] + bv0.w;
        o1.x = acc[i][4] + bv1.x; o1.y = acc[i][5] + bv1.y;
        o1.z = acc[i][6] + bv1.z; o1.w = acc[i][7] + bv1.w;
        *(float4*)(yp) = o0;
        *(float4*)(yp + 4) = o1;
    }
}

// ---------------------------------------------------------------------------
extern "C" void kernel_launch(void* const* d_in, const int* in_sizes, int n_in,
                              void* d_out, int out_size) {
    const float* x      = (const float*)d_in[0];
    const float* theta  = (const float*)d_in[1];
    const float* W0     = (const float*)d_in[2];
    const float* bias   = (const float*)d_in[3];
    const float* BB     = (const float*)d_in[4];
    const float* GG     = (const float*)d_in[5];
    const int*   Pi     = (const int*)d_in[6];   // int32: JAX x64 disabled
    float* y = (float*)d_out;
    const int ntheta = in_sizes[1];

    float* v = nullptr;
    float* u = nullptr;
    cudaGetSymbolAddress((void**)&v, g_v);
    cudaGetSymbolAddress((void**)&u, g_u);

    // Fastfood weight construction
    k_init<<<LL / 256, 256>>>(theta, BB, ntheta);
    k_fwht_rows<<<1024, 256>>>(v);
    k_fwht_cols<<<1024, 256>>>(v);
    k_gather<<<LL / 256, 256>>>(Pi, GG);
    k_fwht_rows<<<1024, 256>>>(u);
    k_fwht_cols<<<1024, 256>>>(u);
    k_reduce1<<<1024, 256>>>(GG);
    k_reduce2<<<1, 256>>>();
    k_makeW<<<DD / 256, 256>>>(W0);

    // GEMM + bias
    dim3 grid(OUTF / 128, MTOT / 128);
    k_gemm<<<grid, 256>>>(x, bias, y);
}

// round 4
// speedup vs baseline: 1.7159x; 1.7159x over previous
#include <cuda_runtime.h>
#include <cuda_bf16.h>
#include <cstdint>

// ---------------------------------------------------------------------------
// GlobalIntrinsicLinear: y = x @ (W0 + Fastfood(theta))^T + b
// GEMM on tensor cores via legacy mma.sync (bf16, fp32 accum), 3-term split:
//   Y = Xhi*Whi + Xhi*Wlo + Xlo*Whi   (~1e-5 rel err)
// Operands stored compact: A' = [Xhi | Xlo] (M x 1536), B' = [Whi | Wlo]
// (N x 1536); the 36 K-tiles remap their source offsets per term.
// ---------------------------------------------------------------------------

#define LL   (1 << 20)
#define DD   (1024 * 768)
#define OUTF 1024
#define INF  768
#define MTOT 16384
#define KA   1536          // 2 * 768 storage K
#define NKT  36            // logical k-tiles (3 terms * 12)

#define BM 128
#define BN 256
#define BK 64
#define RSB 144            // smem row stride bytes (128B data + 16B pad)
#define A_STAGE (BM * RSB) // 18432
#define B_STAGE (BN * RSB) // 36864
#define STAGE   (A_STAGE + B_STAGE)
#define NSTAGE  3

// Scratch (device globals; no cudaMalloc allowed)
__device__ float g_v[LL];
__device__ float g_u[LL];
__device__ float g_part[1024];
__device__ float g_scale;
__device__ __align__(16) __nv_bfloat16 g_A[(size_t)MTOT * KA];   // 50.3 MB
__device__ __align__(16) __nv_bfloat16 g_B[(size_t)OUTF * KA];   // 3 MB

// ======================= PTX helpers =======================================
__device__ __forceinline__ uint32_t smem_u32(const void* p) {
    uint32_t a;
    asm("{ .reg .u64 t; cvta.to.shared.u64 t, %1; cvt.u32.u64 %0, t; }" : "=r"(a) : "l"(p));
    return a;
}

__device__ __forceinline__ void cp_async16(uint32_t dst, const void* src) {
    asm volatile("cp.async.cg.shared.global [%0], [%1], 16;" :: "r"(dst), "l"(src));
}
#define CP_COMMIT() asm volatile("cp.async.commit_group;" ::: "memory")
template <int N>
__device__ __forceinline__ void cp_wait() {
    asm volatile("cp.async.wait_group %0;" :: "n"(N) : "memory");
}

__device__ __forceinline__ void ldmat_x4(uint32_t& r0, uint32_t& r1, uint32_t& r2,
                                         uint32_t& r3, uint32_t addr) {
    asm volatile("ldmatrix.sync.aligned.m8n8.x4.shared.b16 {%0,%1,%2,%3}, [%4];"
                 : "=r"(r0), "=r"(r1), "=r"(r2), "=r"(r3) : "r"(addr));
}

__device__ __forceinline__ void mma16816(float* d, const uint32_t* a,
                                         uint32_t b0, uint32_t b1) {
    asm volatile(
        "mma.sync.aligned.m16n8k16.row.col.f32.bf16.bf16.f32 "
        "{%0,%1,%2,%3}, {%4,%5,%6,%7}, {%8,%9}, {%0,%1,%2,%3};"
        : "+f"(d[0]), "+f"(d[1]), "+f"(d[2]), "+f"(d[3])
        : "r"(a[0]), "r"(a[1]), "r"(a[2]), "r"(a[3]), "r"(b0), "r"(b1));
}

// ======================= Fastfood kernels ==================================
__global__ void k_init(const float* __restrict__ theta, const float* __restrict__ BB,
                       int ntheta) {
    int i = blockIdx.x * blockDim.x + threadIdx.x;
    if (i < LL) {
        float t = (i < ntheta) ? theta[i] : 0.0f;
        g_v[i] = BB[i] * t;
    }
}

__global__ void k_fwht_rows(float* __restrict__ v) {
    __shared__ float s[1024];
    float* p = v + (size_t)blockIdx.x * 1024;
    for (int i = threadIdx.x; i < 1024; i += 256) s[i] = p[i];
    __syncthreads();
#pragma unroll
    for (int h = 1; h < 1024; h <<= 1) {
        for (int idx = threadIdx.x; idx < 512; idx += 256) {
            int j = ((idx & ~(h - 1)) << 1) | (idx & (h - 1));
            float a = s[j], b = s[j + h];
            s[j] = a + b;
            s[j + h] = a - b;
        }
        __syncthreads();
    }
    for (int i = threadIdx.x; i < 1024; i += 256) p[i] = s[i];
}

__global__ void k_fwht_cols(float* __restrict__ v) {
    __shared__ float s[1024];
    int col = blockIdx.x;
    for (int i = threadIdx.x; i < 1024; i += 256) s[i] = v[(size_t)i * 1024 + col];
    __syncthreads();
#pragma unroll
    for (int h = 1; h < 1024; h <<= 1) {
        for (int idx = threadIdx.x; idx < 512; idx += 256) {
            int j = ((idx & ~(h - 1)) << 1) | (idx & (h - 1));
            float a = s[j], b = s[j + h];
            s[j] = a + b;
            s[j + h] = a - b;
        }
        __syncthreads();
    }
    for (int i = threadIdx.x; i < 1024; i += 256) v[(size_t)i * 1024 + col] = s[i];
}

__global__ void k_gather(const int* __restrict__ Pi, const float* __restrict__ GG) {
    int i = blockIdx.x * blockDim.x + threadIdx.x;
    if (i < LL) {
        int idx = Pi[i] & (LL - 1);
        g_u[i] = g_v[idx] * GG[i];
    }
}

__global__ void k_reduce1(const float* __restrict__ GG) {
    __shared__ float sm[256];
    int base = blockIdx.x * 1024;
    float s = 0.0f;
    for (int i = threadIdx.x; i < 1024; i += 256) {
        float g = GG[base + i];
        s += g * g;
    }
    sm[threadIdx.x] = s;
    __syncthreads();
    for (int st = 128; st > 0; st >>= 1) {
        if (threadIdx.x < st) sm[threadIdx.x] += sm[threadIdx.x + st];
        __syncthreads();
    }
    if (threadIdx.x == 0) g_part[blockIdx.x] = sm[0];
}

__global__ void k_reduce2() {
    __shared__ float sm[256];
    float s = 0.0f;
    for (int i = threadIdx.x; i < 1024; i += 256) s += g_part[i];
    sm[threadIdx.x] = s;
    __syncthreads();
    for (int st = 128; st > 0; st >>= 1) {
        if (threadIdx.x < st) sm[threadIdx.x] += sm[threadIdx.x + st];
        __syncthreads();
    }
    if (threadIdx.x == 0) g_scale = 1.0f / sqrtf(sm[0] * (float)DD);
}

// ======================= Operand prep ======================================
// A' = [Xhi | Xlo]
__global__ void k_split_x(const float* __restrict__ X) {
    int i = blockIdx.x * blockDim.x + threadIdx.x;
    if (i < MTOT * INF) {
        int m = i / INF, k = i - m * INF;
        float x = X[i];
        __nv_bfloat16 hi = __float2bfloat16(x);
        __nv_bfloat16 lo = __float2bfloat16(x - __bfloat162float(hi));
        size_t base = (size_t)m * KA + k;
        g_A[base] = hi;
        g_A[base + INF] = lo;
    }
}

// B' = [Whi | Wlo], W = W0 + u * scale
__global__ void k_build_B(const float* __restrict__ W0) {
    int i = blockIdx.x * blockDim.x + threadIdx.x;
    if (i < DD) {
        int n = i / INF, k = i - n * INF;
        float w = W0[i] + g_u[i] * g_scale;
        __nv_bfloat16 hi = __float2bfloat16(w);
        __nv_bfloat16 lo = __float2bfloat16(w - __bfloat162float(hi));
        size_t base = (size_t)n * KA + k;
        g_B[base] = hi;
        g_B[base + INF] = lo;
    }
}

// ======================= mma.sync GEMM =====================================
// CTA 128x256, BK=64, 8 warps (2m x 4n), warp tile 64x64.
// 3-stage cp.async pipeline. Logical K = 36 tiles with per-term remapping.

__device__ __forceinline__ void load_stage(uint32_t sb, const __nv_bfloat16* gA,
                                           const __nv_bfloat16* gB, int t, int tid) {
    int a_k = ((t < 12) ? t : t - 12) * BK;
    int b_k = ((t < 24) ? t : t - 24) * BK;
    uint32_t Ab = sb;
    uint32_t Bb = sb + A_STAGE;
#pragma unroll
    for (int j = 0; j < 4; j++) {       // A: 128 rows * 8 chunks = 1024
        int ca = tid + j * 256;
        int r = ca >> 3, c = ca & 7;
        cp_async16(Ab + r * RSB + c * 16, gA + (size_t)r * KA + a_k + c * 8);
    }
#pragma unroll
    for (int j = 0; j < 8; j++) {       // B: 256 rows * 8 chunks = 2048
        int ca = tid + j * 256;
        int r = ca >> 3, c = ca & 7;
        cp_async16(Bb + r * RSB + c * 16, gB + (size_t)r * KA + b_k + c * 8);
    }
    CP_COMMIT();
}

__global__ __launch_bounds__(256, 1) void k_gemm(const float* __restrict__ bias,
                                                 float* __restrict__ Y) {
    extern __shared__ char dyn[];
    const uint32_t sbase = smem_u32(dyn);
    const int tid = threadIdx.x;
    const int wid = tid >> 5;
    const int lane = tid & 31;
    const int wm = wid & 1;      // 2 m-warps
    const int wn = wid >> 1;     // 4 n-warps
    const int mBase = blockIdx.y * BM;
    const int nBase = blockIdx.x * BN;

    const __nv_bfloat16* gA = g_A + (size_t)mBase * KA;
    const __nv_bfloat16* gB = g_B + (size_t)nBase * KA;

    float acc[4][8][4];
#pragma unroll
    for (int i = 0; i < 4; i++)
#pragma unroll
        for (int j = 0; j < 8; j++)
#pragma unroll
            for (int q = 0; q < 4; q++) acc[i][j][q] = 0.0f;

    // per-lane ldmatrix address components
    const uint32_t aOff = (uint32_t)(wm * 64 + (lane & 15)) * RSB + ((lane >> 4) << 4);
    const uint32_t bOff = (uint32_t)(wn * 64 + (lane & 7) + ((lane >> 4) << 3)) * RSB +
                          (((lane >> 3) & 1) << 4);

    load_stage(sbase, gA, gB, 0, tid);
    load_stage(sbase + STAGE, gA, gB, 1, tid);

    for (int t = 0; t < NKT; t++) {
        cp_wait<1>();
        __syncthreads();
        if (t + 2 < NKT)
            load_stage(sbase + ((t + 2) % NSTAGE) * STAGE, gA, gB, t + 2, tid);

        const uint32_t Ab = sbase + (t % NSTAGE) * STAGE + aOff;
        const uint32_t Bb = sbase + (t % NSTAGE) * STAGE + A_STAGE + bOff;
#pragma unroll
        for (int kk = 0; kk < 4; kk++) {
            uint32_t a[4][4];
            uint32_t b[4][4];   // b[jp]: {b0 fragj, b1 fragj, b0 fragj+1, b1 fragj+1}
#pragma unroll
            for (int im = 0; im < 4; im++)
                ldmat_x4(a[im][0], a[im][1], a[im][2], a[im][3],
                         Ab + im * (16 * RSB) + kk * 32);
#pragma unroll
            for (int jp = 0; jp < 4; jp++)
                ldmat_x4(b[jp][0], b[jp][1], b[jp][2], b[jp][3],
                         Bb + jp * (16 * RSB) + kk * 32);
#pragma unroll
            for (int im = 0; im < 4; im++)
#pragma unroll
                for (int jp = 0; jp < 4; jp++) {
                    mma16816(acc[im][2 * jp + 0], a[im], b[jp][0], b[jp][1]);
                    mma16816(acc[im][2 * jp + 1], a[im], b[jp][2], b[jp][3]);
                }
        }
        __syncthreads();
    }

    // Epilogue: fp32 + bias, 64-bit stores
    const int row0 = mBase + wm * 64 + (lane >> 2);
    const int col0 = nBase + wn * 64 + (lane & 3) * 2;
#pragma unroll
    for (int im = 0; im < 4; im++) {
        int r = row0 + im * 16;
#pragma unroll
        for (int jn = 0; jn < 8; jn++) {
            int c = col0 + jn * 8;
            float2 bv = *(const float2*)(bias + c);
            float2 o0, o1;
            o0.x = acc[im][jn][0] + bv.x;
            o0.y = acc[im][jn][1] + bv.y;
            o1.x = acc[im][jn][2] + bv.x;
            o1.y = acc[im][jn][3] + bv.y;
            *(float2*)(Y + (size_t)r * OUTF + c) = o0;
            *(float2*)(Y + (size_t)(r + 8) * OUTF + c) = o1;
        }
    }
}

// ---------------------------------------------------------------------------
extern "C" void kernel_launch(void* const* d_in, const int* in_sizes, int n_in,
                              void* d_out, int out_size) {
    const float* x     = (const float*)d_in[0];
    const float* theta = (const float*)d_in[1];
    const float* W0    = (const float*)d_in[2];
    const float* bias  = (const float*)d_in[3];
    const float* BB    = (const float*)d_in[4];
    const float* GG    = (const float*)d_in[5];
    const int*   Pi    = (const int*)d_in[6];   // int32 (JAX x64 disabled)
    float* y = (float*)d_out;
    const int ntheta = in_sizes[1];

    float* v = nullptr;
    float* u = nullptr;
    cudaGetSymbolAddress((void**)&v, g_v);
    cudaGetSymbolAddress((void**)&u, g_u);

    cudaFuncSetAttribute(k_gemm, cudaFuncAttributeMaxDynamicSharedMemorySize,
                         NSTAGE * STAGE);

    // Fastfood weight construction
    k_init<<<LL / 256, 256>>>(theta, BB, ntheta);
    k_fwht_rows<<<1024, 256>>>(v);
    k_fwht_cols<<<1024, 256>>>(v);
    k_gather<<<LL / 256, 256>>>(Pi, GG);
    k_fwht_rows<<<1024, 256>>>(u);
    k_fwht_cols<<<1024, 256>>>(u);
    k_reduce1<<<1024, 256>>>(GG);
    k_reduce2<<<1, 256>>>();

    // Split-bf16 operand prep
    k_split_x<<<(MTOT * INF + 255) / 256, 256>>>(x);
    k_build_B<<<(DD + 255) / 256, 256>>>(W0);

    // Tensor-core GEMM + bias
    dim3 grid(OUTF / BN, MTOT / BM);
    k_gemm<<<grid, 256, NSTAGE * STAGE>>>(bias, y);
}

// round 5
// speedup vs baseline: 2.0480x; 1.1935x over previous
#include <cuda_runtime.h>
#include <cuda_bf16.h>
#include <cstdint>

// ---------------------------------------------------------------------------
// GlobalIntrinsicLinear: y = x @ (W0 + Fastfood(theta))^T + b
// Key identity: theta occupies only rows 0,1 of the 1024x1024 FWHT view, so
// the first full 2^20 FWHT collapses to  v[r,c] = a[c] + (-1)^(r&1) b[c]
// with a = FWHT1024(BB*theta row0), b = FWHT1024(row1).
// GEMM: mma.sync bf16 3-term split  Y = Xhi*Whi + Xhi*Wlo + Xlo*Whi.
// ---------------------------------------------------------------------------

#define LL   (1 << 20)
#define DD   (1024 * 768)
#define OUTF 1024
#define INF  768
#define MTOT 16384
#define KA   1536          // 2 * 768 storage K
#define NKT  36            // logical k-tiles (3 terms * 12)

#define BM 128
#define BN 256
#define BK 64
#define RSB 144            // smem row stride bytes (128B data + 16B pad)
#define A_STAGE (BM * RSB) // 18432
#define B_STAGE (BN * RSB) // 36864
#define STAGE   (A_STAGE + B_STAGE)
#define NSTAGE  4

// Scratch (device globals; no cudaMalloc allowed)
__device__ float g_a[1024];
__device__ float g_b[1024];
__device__ float g_u[LL];
__device__ float g_part[1024];
__device__ float g_scale;
__device__ __align__(16) __nv_bfloat16 g_A[(size_t)MTOT * KA];   // 50.3 MB
__device__ __align__(16) __nv_bfloat16 g_B[(size_t)OUTF * KA];   // 3 MB

// ======================= PTX helpers =======================================
__device__ __forceinline__ uint32_t smem_u32(const void* p) {
    uint32_t a;
    asm("{ .reg .u64 t; cvta.to.shared.u64 t, %1; cvt.u32.u64 %0, t; }" : "=r"(a) : "l"(p));
    return a;
}

__device__ __forceinline__ void cp_async16(uint32_t dst, const void* src) {
    asm volatile("cp.async.cg.shared.global [%0], [%1], 16;" :: "r"(dst), "l"(src));
}
#define CP_COMMIT() asm volatile("cp.async.commit_group;" ::: "memory")
template <int N>
__device__ __forceinline__ void cp_wait() {
    asm volatile("cp.async.wait_group %0;" :: "n"(N) : "memory");
}

__device__ __forceinline__ void ldmat_x4(uint32_t& r0, uint32_t& r1, uint32_t& r2,
                                         uint32_t& r3, uint32_t addr) {
    asm volatile("ldmatrix.sync.aligned.m8n8.x4.shared.b16 {%0,%1,%2,%3}, [%4];"
                 : "=r"(r0), "=r"(r1), "=r"(r2), "=r"(r3) : "r"(addr));
}

__device__ __forceinline__ void mma16816(float* d, const uint32_t* a,
                                         uint32_t b0, uint32_t b1) {
    asm volatile(
        "mma.sync.aligned.m16n8k16.row.col.f32.bf16.bf16.f32 "
        "{%0,%1,%2,%3}, {%4,%5,%6,%7}, {%8,%9}, {%0,%1,%2,%3};"
        : "+f"(d[0]), "+f"(d[1]), "+f"(d[2]), "+f"(d[3])
        : "r"(a[0]), "r"(a[1]), "r"(a[2]), "r"(a[3]), "r"(b0), "r"(b1));
}

// ======================= Fastfood kernels ==================================
// In-smem FWHT over 1024 floats, 256 threads
__device__ __forceinline__ void fwht1024_smem(float* s) {
#pragma unroll
    for (int h = 1; h < 1024; h <<= 1) {
        for (int idx = threadIdx.x; idx < 512; idx += 256) {
            int j = ((idx & ~(h - 1)) << 1) | (idx & (h - 1));
            float a = s[j], b = s[j + h];
            s[j] = a + b;
            s[j + h] = a - b;
        }
        __syncthreads();
    }
}

// block 0 -> a = FWHT(BB[0:1024]*theta[0:1024]); block 1 -> b (next 1024)
__global__ void k_ab(const float* __restrict__ theta, const float* __restrict__ BB,
                     int ntheta) {
    __shared__ float s[1024];
    const int gbase = blockIdx.x * 1024;
    for (int j = threadIdx.x; j < 1024; j += 256) {
        int gi = gbase + j;
        float t = (gi < ntheta) ? theta[gi] : 0.0f;
        s[j] = BB[gi] * t;
    }
    __syncthreads();
    fwht1024_smem(s);
    float* dst = (blockIdx.x == 0) ? g_a : g_b;
    for (int j = threadIdx.x; j < 1024; j += 256) dst[j] = s[j];
}

// Fused: u_row[j] = (a[c] +/- b[c]) * GG[.]  (gather from smem), then
// row-FWHT, write g_u row; also per-block sum of GG^2 -> g_part.
__global__ void k_gather_rows(const int* __restrict__ Pi, const float* __restrict__ GG) {
    __shared__ float sa[1024], sb[1024], sr[1024];
    __shared__ float red[256];
    const int base = blockIdx.x * 1024;
    for (int j = threadIdx.x; j < 1024; j += 256) {
        sa[j] = g_a[j];
        sb[j] = g_b[j];
    }
    __syncthreads();
    float gsum = 0.0f;
    for (int j = threadIdx.x; j < 1024; j += 256) {
        int idx = Pi[base + j] & (LL - 1);
        int c = idx & 1023;
        float v = sa[c] + (((idx >> 10) & 1) ? -sb[c] : sb[c]);
        float g = GG[base + j];
        gsum += g * g;
        sr[j] = v * g;
    }
    __syncthreads();
    fwht1024_smem(sr);
    for (int j = threadIdx.x; j < 1024; j += 256) g_u[base + j] = sr[j];
    red[threadIdx.x] = gsum;
    __syncthreads();
    for (int st = 128; st > 0; st >>= 1) {
        if (threadIdx.x < st) red[threadIdx.x] += red[threadIdx.x + st];
        __syncthreads();
    }
    if (threadIdx.x == 0) g_part[blockIdx.x] = red[0];
}

__global__ void k_reduce2() {
    __shared__ float sm[256];
    float s = 0.0f;
    for (int i = threadIdx.x; i < 1024; i += 256) s += g_part[i];
    sm[threadIdx.x] = s;
    __syncthreads();
    for (int st = 128; st > 0; st >>= 1) {
        if (threadIdx.x < st) sm[threadIdx.x] += sm[threadIdx.x + st];
        __syncthreads();
    }
    if (threadIdx.x == 0) g_scale = 1.0f / sqrtf(sm[0] * (float)DD);
}

// Column FWHT (high 10 bits), 8 columns per block for full-sector loads
__global__ void k_fwht_cols8(float* __restrict__ v) {
    __shared__ float s[1024][8];
    const int c0 = blockIdx.x * 8;
    for (int j = threadIdx.x; j < 2048; j += 256) {
        int row = j >> 1, half = j & 1;
        float4 t = *(const float4*)(v + (size_t)row * 1024 + c0 + half * 4);
        s[row][half * 4 + 0] = t.x;
        s[row][half * 4 + 1] = t.y;
        s[row][half * 4 + 2] = t.z;
        s[row][half * 4 + 3] = t.w;
    }
    __syncthreads();
#pragma unroll
    for (int h = 1; h < 1024; h <<= 1) {
        for (int p = threadIdx.x; p < 4096; p += 256) {
            int pi = p >> 3, cc = p & 7;
            int j = ((pi & ~(h - 1)) << 1) | (pi & (h - 1));
            float x = s[j][cc], y = s[j + h][cc];
            s[j][cc] = x + y;
            s[j + h][cc] = x - y;
        }
        __syncthreads();
    }
    for (int j = threadIdx.x; j < 2048; j += 256) {
        int row = j >> 1, half = j & 1;
        float4 t;
        t.x = s[row][half * 4 + 0];
        t.y = s[row][half * 4 + 1];
        t.z = s[row][half * 4 + 2];
        t.w = s[row][half * 4 + 3];
        *(float4*)(v + (size_t)row * 1024 + c0 + half * 4) = t;
    }
}

// ======================= Operand prep ======================================
__device__ __forceinline__ uint32_t pack_bf16x2(float x, float y) {
    __nv_bfloat162 h(__float2bfloat16(x), __float2bfloat16(y));
    return *(uint32_t*)&h;
}

// A' = [Xhi | Xlo], vectorized 4 elements/thread
__global__ void k_split_x(const float* __restrict__ X) {
    int i4 = blockIdx.x * blockDim.x + threadIdx.x;
    if (i4 < MTOT * INF / 4) {
        int m = i4 / (INF / 4);
        int k = (i4 - m * (INF / 4)) * 4;
        float4 xv = *(const float4*)(X + (size_t)m * INF + k);
        float hx = __bfloat162float(__float2bfloat16(xv.x));
        float hy = __bfloat162float(__float2bfloat16(xv.y));
        float hz = __bfloat162float(__float2bfloat16(xv.z));
        float hw = __bfloat162float(__float2bfloat16(xv.w));
        uint2 hi, lo;
        hi.x = pack_bf16x2(xv.x, xv.y);
        hi.y = pack_bf16x2(xv.z, xv.w);
        lo.x = pack_bf16x2(xv.x - hx, xv.y - hy);
        lo.y = pack_bf16x2(xv.z - hz, xv.w - hw);
        size_t base = (size_t)m * KA + k;
        *(uint2*)(g_A + base) = hi;
        *(uint2*)(g_A + base + INF) = lo;
    }
}

// B' = [Whi | Wlo], W = W0 + u * scale
__global__ void k_build_B(const float* __restrict__ W0) {
    int i4 = blockIdx.x * blockDim.x + threadIdx.x;
    if (i4 < DD / 4) {
        int n = i4 / (INF / 4);
        int k = (i4 - n * (INF / 4)) * 4;
        size_t gi = (size_t)n * INF + k;
        float4 w0 = *(const float4*)(W0 + gi);
        float4 uv = *(const float4*)(g_u + gi);
        float sc = g_scale;
        float wx = w0.x + uv.x * sc, wy = w0.y + uv.y * sc;
        float wz = w0.z + uv.z * sc, ww = w0.w + uv.w * sc;
        float hx = __bfloat162float(__float2bfloat16(wx));
        float hy = __bfloat162float(__float2bfloat16(wy));
        float hz = __bfloat162float(__float2bfloat16(wz));
        float hw = __bfloat162float(__float2bfloat16(ww));
        uint2 hi, lo;
        hi.x = pack_bf16x2(wx, wy);
        hi.y = pack_bf16x2(wz, ww);
        lo.x = pack_bf16x2(wx - hx, wy - hy);
        lo.y = pack_bf16x2(wz - hz, ww - hw);
        size_t base = (size_t)n * KA + k;
        *(uint2*)(g_B + base) = hi;
        *(uint2*)(g_B + base + INF) = lo;
    }
}

// ======================= mma.sync GEMM =====================================
// CTA 128x256, BK=64, 8 warps (2m x 4n), warp tile 64x64.
// 4-stage cp.async ring, one __syncthreads per k-tile.
// Logical K = 36 tiles with per-term source remapping.

__device__ __forceinline__ void load_stage(uint32_t sb, const __nv_bfloat16* gA,
                                           const __nv_bfloat16* gB, int t, int tid) {
    int a_k = ((t < 12) ? t : t - 12) * BK;
    int b_k = ((t < 24) ? t : t - 24) * BK;
    uint32_t Ab = sb;
    uint32_t Bb = sb + A_STAGE;
#pragma unroll
    for (int j = 0; j < 4; j++) {       // A: 128 rows * 8 chunks = 1024
        int ca = tid + j * 256;
        int r = ca >> 3, c = ca & 7;
        cp_async16(Ab + r * RSB + c * 16, gA + (size_t)r * KA + a_k + c * 8);
    }
#pragma unroll
    for (int j = 0; j < 8; j++) {       // B: 256 rows * 8 chunks = 2048
        int ca = tid + j * 256;
        int r = ca >> 3, c = ca & 7;
        cp_async16(Bb + r * RSB + c * 16, gB + (size_t)r * KA + b_k + c * 8);
    }
    CP_COMMIT();
}

__global__ __launch_bounds__(256, 1) void k_gemm(const float* __restrict__ bias,
                                                 float* __restrict__ Y) {
    extern __shared__ char dyn[];
    const uint32_t sbase = smem_u32(dyn);
    const int tid = threadIdx.x;
    const int wid = tid >> 5;
    const int lane = tid & 31;
    const int wm = wid & 1;      // 2 m-warps
    const int wn = wid >> 1;     // 4 n-warps
    const int mBase = blockIdx.y * BM;
    const int nBase = blockIdx.x * BN;

    const __nv_bfloat16* gA = g_A + (size_t)mBase * KA;
    const __nv_bfloat16* gB = g_B + (size_t)nBase * KA;

    float acc[4][8][4];
#pragma unroll
    for (int i = 0; i < 4; i++)
#pragma unroll
        for (int j = 0; j < 8; j++)
#pragma unroll
            for (int q = 0; q < 4; q++) acc[i][j][q] = 0.0f;

    const uint32_t aOff = (uint32_t)(wm * 64 + (lane & 15)) * RSB + ((lane >> 4) << 4);
    const uint32_t bOff = (uint32_t)(wn * 64 + (lane & 7) + ((lane >> 4) << 3)) * RSB +
                          (((lane >> 3) & 1) << 4);

    load_stage(sbase + 0 * STAGE, gA, gB, 0, tid);
    load_stage(sbase + 1 * STAGE, gA, gB, 1, tid);
    load_stage(sbase + 2 * STAGE, gA, gB, 2, tid);

    for (int t = 0; t < NKT; t++) {
        cp_wait<2>();
        __syncthreads();
        if (t + 3 < NKT)
            load_stage(sbase + ((t + 3) % NSTAGE) * STAGE, gA, gB, t + 3, tid);

        const uint32_t Ab = sbase + (t % NSTAGE) * STAGE + aOff;
        const uint32_t Bb = sbase + (t % NSTAGE) * STAGE + A_STAGE + bOff;
#pragma unroll
        for (int kk = 0; kk < 4; kk++) {
            uint32_t a[4][4];
            uint32_t b[4][4];
#pragma unroll
            for (int im = 0; im < 4; im++)
                ldmat_x4(a[im][0], a[im][1], a[im][2], a[im][3],
                         Ab + im * (16 * RSB) + kk * 32);
#pragma unroll
            for (int jp = 0; jp < 4; jp++)
                ldmat_x4(b[jp][0], b[jp][1], b[jp][2], b[jp][3],
                         Bb + jp * (16 * RSB) + kk * 32);
#pragma unroll
            for (int im = 0; im < 4; im++)
#pragma unroll
                for (int jp = 0; jp < 4; jp++) {
                    mma16816(acc[im][2 * jp + 0], a[im], b[jp][0], b[jp][1]);
                    mma16816(acc[im][2 * jp + 1], a[im], b[jp][2], b[jp][3]);
                }
        }
    }

    // Epilogue: fp32 + bias
    const int row0 = mBase + wm * 64 + (lane >> 2);
    const int col0 = nBase + wn * 64 + (lane & 3) * 2;
#pragma unroll
    for (int im = 0; im < 4; im++) {
        int r = row0 + im * 16;
#pragma unroll
        for (int jn = 0; jn < 8; jn++) {
            int c = col0 + jn * 8;
            float2 bv = *(const float2*)(bias + c);
            float2 o0, o1;
            o0.x = acc[im][jn][0] + bv.x;
            o0.y = acc[im][jn][1] + bv.y;
            o1.x = acc[im][jn][2] + bv.x;
            o1.y = acc[im][jn][3] + bv.y;
            *(float2*)(Y + (size_t)r * OUTF + c) = o0;
            *(float2*)(Y + (size_t)(r + 8) * OUTF + c) = o1;
        }
    }
}

// ---------------------------------------------------------------------------
extern "C" void kernel_launch(void* const* d_in, const int* in_sizes, int n_in,
                              void* d_out, int out_size) {
    const float* x     = (const float*)d_in[0];
    const float* theta = (const float*)d_in[1];
    const float* W0    = (const float*)d_in[2];
    const float* bias  = (const float*)d_in[3];
    const float* BB    = (const float*)d_in[4];
    const float* GG    = (const float*)d_in[5];
    const int*   Pi    = (const int*)d_in[6];   // int32 (JAX x64 disabled)
    float* y = (float*)d_out;
    const int ntheta = in_sizes[1];             // 2048 -> rows 0,1 only

    float* u = nullptr;
    cudaGetSymbolAddress((void**)&u, g_u);

    cudaFuncSetAttribute(k_gemm, cudaFuncAttributeMaxDynamicSharedMemorySize,
                         NSTAGE * STAGE);

    // Fastfood weight construction (pass-1 FWHT collapsed analytically)
    k_ab<<<2, 256>>>(theta, BB, ntheta);
    k_gather_rows<<<1024, 256>>>(Pi, GG);
    k_reduce2<<<1, 256>>>();
    k_fwht_cols8<<<128, 256>>>(u);

    // Split-bf16 operand prep
    k_split_x<<<(MTOT * INF / 4 + 255) / 256, 256>>>(x);
    k_build_B<<<(DD / 4 + 255) / 256, 256>>>(W0);

    // Tensor-core GEMM + bias
    dim3 grid(OUTF / BN, MTOT / BM);
    k_gemm<<<grid, 256, NSTAGE * STAGE>>>(bias, y);
}

// round 6
// speedup vs baseline: 2.3965x; 1.1701x over previous
#include <cuda_runtime.h>
#include <cuda_bf16.h>
#include <cstdint>

// ---------------------------------------------------------------------------
// GlobalIntrinsicLinear: y = x @ (W0 + Fastfood(theta))^T + b
// Pass-1 FWHT collapsed analytically (theta occupies rows 0,1 of the
// 1024x1024 view):  v[r,c] = a[c] + (-1)^(bit10) b[c].
// GEMM: mma.sync bf16 3-term split  Y = Xhi*Whi + Xhi*Wlo + Xlo*Whi,
// stored compact A'=[Xhi|Xlo], B'=[Whi|Wlo], 36 logical k-tiles remapped.
// R6: 128x128 CTA tile, 3-stage cp.async, 2 CTAs/SM for latency hiding.
// ---------------------------------------------------------------------------

#define LL   (1 << 20)
#define DD   (1024 * 768)
#define OUTF 1024
#define INF  768
#define MTOT 16384
#define KA   1536          // 2 * 768 storage K
#define NKT  36            // logical k-tiles (3 terms * 12)

#define BM 128
#define BN 128
#define BK 64
#define RSB 144            // smem row stride bytes (128B data + 16B pad)
#define A_STAGE (BM * RSB) // 18432
#define B_STAGE (BN * RSB) // 18432
#define STAGE   (A_STAGE + B_STAGE)   // 36864
#define NSTAGE  3

// Scratch (device globals; no cudaMalloc allowed)
__device__ float g_a[1024];
__device__ float g_b[1024];
__device__ float g_u[LL];
__device__ float g_part[1024];
__device__ float g_scale;
__device__ __align__(16) __nv_bfloat16 g_A[(size_t)MTOT * KA];   // 50.3 MB
__device__ __align__(16) __nv_bfloat16 g_B[(size_t)OUTF * KA];   // 3 MB

// ======================= PTX helpers =======================================
__device__ __forceinline__ uint32_t smem_u32(const void* p) {
    uint32_t a;
    asm("{ .reg .u64 t; cvta.to.shared.u64 t, %1; cvt.u32.u64 %0, t; }" : "=r"(a) : "l"(p));
    return a;
}

__device__ __forceinline__ void cp_async16(uint32_t dst, const void* src) {
    asm volatile("cp.async.cg.shared.global [%0], [%1], 16;" :: "r"(dst), "l"(src));
}
#define CP_COMMIT() asm volatile("cp.async.commit_group;" ::: "memory")
template <int N>
__device__ __forceinline__ void cp_wait() {
    asm volatile("cp.async.wait_group %0;" :: "n"(N) : "memory");
}

__device__ __forceinline__ void ldmat_x4(uint32_t& r0, uint32_t& r1, uint32_t& r2,
                                         uint32_t& r3, uint32_t addr) {
    asm volatile("ldmatrix.sync.aligned.m8n8.x4.shared.b16 {%0,%1,%2,%3}, [%4];"
                 : "=r"(r0), "=r"(r1), "=r"(r2), "=r"(r3) : "r"(addr));
}

__device__ __forceinline__ void mma16816(float* d, const uint32_t* a,
                                         uint32_t b0, uint32_t b1) {
    asm volatile(
        "mma.sync.aligned.m16n8k16.row.col.f32.bf16.bf16.f32 "
        "{%0,%1,%2,%3}, {%4,%5,%6,%7}, {%8,%9}, {%0,%1,%2,%3};"
        : "+f"(d[0]), "+f"(d[1]), "+f"(d[2]), "+f"(d[3])
        : "r"(a[0]), "r"(a[1]), "r"(a[2]), "r"(a[3]), "r"(b0), "r"(b1));
}

// ======================= Fastfood kernels ==================================
__device__ __forceinline__ void fwht1024_smem(float* s) {
#pragma unroll
    for (int h = 1; h < 1024; h <<= 1) {
        for (int idx = threadIdx.x; idx < 512; idx += 256) {
            int j = ((idx & ~(h - 1)) << 1) | (idx & (h - 1));
            float a = s[j], b = s[j + h];
            s[j] = a + b;
            s[j + h] = a - b;
        }
        __syncthreads();
    }
}

// block 0 -> a = FWHT(BB[0:1024]*theta[0:1024]); block 1 -> b (next 1024)
__global__ void k_ab(const float* __restrict__ theta, const float* __restrict__ BB,
                     int ntheta) {
    __shared__ float s[1024];
    const int gbase = blockIdx.x * 1024;
    for (int j = threadIdx.x; j < 1024; j += 256) {
        int gi = gbase + j;
        float t = (gi < ntheta) ? theta[gi] : 0.0f;
        s[j] = BB[gi] * t;
    }
    __syncthreads();
    fwht1024_smem(s);
    float* dst = (blockIdx.x == 0) ? g_a : g_b;
    for (int j = threadIdx.x; j < 1024; j += 256) dst[j] = s[j];
}

// Fused gather (from smem a,b) + GG mult + row FWHT + GG^2 partial sums
__global__ void k_gather_rows(const int* __restrict__ Pi, const float* __restrict__ GG) {
    __shared__ float sa[1024], sb[1024], sr[1024];
    __shared__ float red[256];
    const int base = blockIdx.x * 1024;
    for (int j = threadIdx.x; j < 1024; j += 256) {
        sa[j] = g_a[j];
        sb[j] = g_b[j];
    }
    __syncthreads();
    float gsum = 0.0f;
    for (int j = threadIdx.x; j < 1024; j += 256) {
        int idx = Pi[base + j] & (LL - 1);
        int c = idx & 1023;
        float v = sa[c] + (((idx >> 10) & 1) ? -sb[c] : sb[c]);
        float g = GG[base + j];
        gsum += g * g;
        sr[j] = v * g;
    }
    __syncthreads();
    fwht1024_smem(sr);
    for (int j = threadIdx.x; j < 1024; j += 256) g_u[base + j] = sr[j];
    red[threadIdx.x] = gsum;
    __syncthreads();
    for (int st = 128; st > 0; st >>= 1) {
        if (threadIdx.x < st) red[threadIdx.x] += red[threadIdx.x + st];
        __syncthreads();
    }
    if (threadIdx.x == 0) g_part[blockIdx.x] = red[0];
}

__global__ void k_reduce2() {
    __shared__ float sm[256];
    float s = 0.0f;
    for (int i = threadIdx.x; i < 1024; i += 256) s += g_part[i];
    sm[threadIdx.x] = s;
    __syncthreads();
    for (int st = 128; st > 0; st >>= 1) {
        if (threadIdx.x < st) sm[threadIdx.x] += sm[threadIdx.x + st];
        __syncthreads();
    }
    if (threadIdx.x == 0) g_scale = 1.0f / sqrtf(sm[0] * (float)DD);
}

// Column FWHT (high 10 bits), 4 columns per block (256 blocks covers chip)
__global__ void k_fwht_cols4(float* __restrict__ v) {
    __shared__ float s[1024][4];
    const int c0 = blockIdx.x * 4;
    for (int row = threadIdx.x; row < 1024; row += 256) {
        float4 t = *(const float4*)(v + (size_t)row * 1024 + c0);
        s[row][0] = t.x; s[row][1] = t.y; s[row][2] = t.z; s[row][3] = t.w;
    }
    __syncthreads();
#pragma unroll
    for (int h = 1; h < 1024; h <<= 1) {
        for (int p = threadIdx.x; p < 2048; p += 256) {
            int pi = p >> 2, cc = p & 3;
            int j = ((pi & ~(h - 1)) << 1) | (pi & (h - 1));
            float x = s[j][cc], y = s[j + h][cc];
            s[j][cc] = x + y;
            s[j + h][cc] = x - y;
        }
        __syncthreads();
    }
    for (int row = threadIdx.x; row < 1024; row += 256) {
        float4 t;
        t.x = s[row][0]; t.y = s[row][1]; t.z = s[row][2]; t.w = s[row][3];
        *(float4*)(v + (size_t)row * 1024 + c0) = t;
    }
}

// ======================= Operand prep ======================================
__device__ __forceinline__ uint32_t pack_bf16x2(float x, float y) {
    __nv_bfloat162 h(__float2bfloat16(x), __float2bfloat16(y));
    return *(uint32_t*)&h;
}

// A' = [Xhi | Xlo]
__global__ void k_split_x(const float* __restrict__ X) {
    int i4 = blockIdx.x * blockDim.x + threadIdx.x;
    if (i4 < MTOT * INF / 4) {
        int m = i4 / (INF / 4);
        int k = (i4 - m * (INF / 4)) * 4;
        float4 xv = *(const float4*)(X + (size_t)m * INF + k);
        float hx = __bfloat162float(__float2bfloat16(xv.x));
        float hy = __bfloat162float(__float2bfloat16(xv.y));
        float hz = __bfloat162float(__float2bfloat16(xv.z));
        float hw = __bfloat162float(__float2bfloat16(xv.w));
        uint2 hi, lo;
        hi.x = pack_bf16x2(xv.x, xv.y);
        hi.y = pack_bf16x2(xv.z, xv.w);
        lo.x = pack_bf16x2(xv.x - hx, xv.y - hy);
        lo.y = pack_bf16x2(xv.z - hz, xv.w - hw);
        size_t base = (size_t)m * KA + k;
        *(uint2*)(g_A + base) = hi;
        *(uint2*)(g_A + base + INF) = lo;
    }
}

// B' = [Whi | Wlo], W = W0 + u * scale
__global__ void k_build_B(const float* __restrict__ W0) {
    int i4 = blockIdx.x * blockDim.x + threadIdx.x;
    if (i4 < DD / 4) {
        int n = i4 / (INF / 4);
        int k = (i4 - n * (INF / 4)) * 4;
        size_t gi = (size_t)n * INF + k;
        float4 w0 = *(const float4*)(W0 + gi);
        float4 uv = *(const float4*)(g_u + gi);
        float sc = g_scale;
        float wx = w0.x + uv.x * sc, wy = w0.y + uv.y * sc;
        float wz = w0.z + uv.z * sc, ww = w0.w + uv.w * sc;
        float hx = __bfloat162float(__float2bfloat16(wx));
        float hy = __bfloat162float(__float2bfloat16(wy));
        float hz = __bfloat162float(__float2bfloat16(wz));
        float hw = __bfloat162float(__float2bfloat16(ww));
        uint2 hi, lo;
        hi.x = pack_bf16x2(wx, wy);
        hi.y = pack_bf16x2(wz, ww);
        lo.x = pack_bf16x2(wx - hx, wy - hy);
        lo.y = pack_bf16x2(wz - hz, ww - hw);
        size_t base = (size_t)n * KA + k;
        *(uint2*)(g_B + base) = hi;
        *(uint2*)(g_B + base + INF) = lo;
    }
}

// ======================= mma.sync GEMM =====================================
// CTA 128x128, BK=64, 8 warps (2m x 4n), warp tile 64x32.
// 3-stage cp.async ring, 2 CTAs/SM. Logical K = 36 remapped tiles.

__device__ __forceinline__ void load_stage(uint32_t sb, const __nv_bfloat16* gA,
                                           const __nv_bfloat16* gB, int t, int tid) {
    int a_k = ((t < 12) ? t : t - 12) * BK;
    int b_k = ((t < 24) ? t : t - 24) * BK;
    uint32_t Ab = sb;
    uint32_t Bb = sb + A_STAGE;
#pragma unroll
    for (int j = 0; j < 4; j++) {       // A: 128 rows * 8 chunks = 1024
        int ca = tid + j * 256;
        int r = ca >> 3, c = ca & 7;
        cp_async16(Ab + r * RSB + c * 16, gA + (size_t)r * KA + a_k + c * 8);
    }
#pragma unroll
    for (int j = 0; j < 4; j++) {       // B: 128 rows * 8 chunks = 1024
        int ca = tid + j * 256;
        int r = ca >> 3, c = ca & 7;
        cp_async16(Bb + r * RSB + c * 16, gB + (size_t)r * KA + b_k + c * 8);
    }
    CP_COMMIT();
}

__global__ __launch_bounds__(256, 2) void k_gemm(const float* __restrict__ bias,
                                                 float* __restrict__ Y) {
    extern __shared__ char dyn[];
    const uint32_t sbase = smem_u32(dyn);
    const int tid = threadIdx.x;
    const int wid = tid >> 5;
    const int lane = tid & 31;
    const int wm = wid & 1;      // 2 m-warps (64 rows each)
    const int wn = wid >> 1;     // 4 n-warps (32 cols each)
    const int mBase = blockIdx.y * BM;
    const int nBase = blockIdx.x * BN;

    const __nv_bfloat16* gA = g_A + (size_t)mBase * KA;
    const __nv_bfloat16* gB = g_B + (size_t)nBase * KA;

    float acc[4][4][4];
#pragma unroll
    for (int i = 0; i < 4; i++)
#pragma unroll
        for (int j = 0; j < 4; j++)
#pragma unroll
            for (int q = 0; q < 4; q++) acc[i][j][q] = 0.0f;

    const uint32_t aOff = (uint32_t)(wm * 64 + (lane & 15)) * RSB + ((lane >> 4) << 4);
    const uint32_t bOff = (uint32_t)(wn * 32 + (lane & 7) + ((lane >> 4) << 3)) * RSB +
                          (((lane >> 3) & 1) << 4);

    load_stage(sbase + 0 * STAGE, gA, gB, 0, tid);
    load_stage(sbase + 1 * STAGE, gA, gB, 1, tid);

    for (int t = 0; t < NKT; t++) {
        cp_wait<1>();
        __syncthreads();
        if (t + 2 < NKT)
            load_stage(sbase + ((t + 2) % NSTAGE) * STAGE, gA, gB, t + 2, tid);

        const uint32_t Ab = sbase + (t % NSTAGE) * STAGE + aOff;
        const uint32_t Bb = sbase + (t % NSTAGE) * STAGE + A_STAGE + bOff;
#pragma unroll
        for (int kk = 0; kk < 4; kk++) {
            uint32_t a[4][4];
            uint32_t b[2][4];
#pragma unroll
            for (int im = 0; im < 4; im++)
                ldmat_x4(a[im][0], a[im][1], a[im][2], a[im][3],
                         Ab + im * (16 * RSB) + kk * 32);
#pragma unroll
            for (int jp = 0; jp < 2; jp++)
                ldmat_x4(b[jp][0], b[jp][1], b[jp][2], b[jp][3],
                         Bb + jp * (16 * RSB) + kk * 32);
#pragma unroll
            for (int im = 0; im < 4; im++)
#pragma unroll
                for (int jp = 0; jp < 2; jp++) {
                    mma16816(acc[im][2 * jp + 0], a[im], b[jp][0], b[jp][1]);
                    mma16816(acc[im][2 * jp + 1], a[im], b[jp][2], b[jp][3]);
                }
        }
    }

    // Epilogue: fp32 + bias
    const int row0 = mBase + wm * 64 + (lane >> 2);
    const int col0 = nBase + wn * 32 + (lane & 3) * 2;
#pragma unroll
    for (int im = 0; im < 4; im++) {
        int r = row0 + im * 16;
#pragma unroll
        for (int jn = 0; jn < 4; jn++) {
            int c = col0 + jn * 8;
            float2 bv = *(const float2*)(bias + c);
            float2 o0, o1;
            o0.x = acc[im][jn][0] + bv.x;
            o0.y = acc[im][jn][1] + bv.y;
            o1.x = acc[im][jn][2] + bv.x;
            o1.y = acc[im][jn][3] + bv.y;
            *(float2*)(Y + (size_t)r * OUTF + c) = o0;
            *(float2*)(Y + (size_t)(r + 8) * OUTF + c) = o1;
        }
    }
}

// ---------------------------------------------------------------------------
extern "C" void kernel_launch(void* const* d_in, const int* in_sizes, int n_in,
                              void* d_out, int out_size) {
    const float* x     = (const float*)d_in[0];
    const float* theta = (const float*)d_in[1];
    const float* W0    = (const float*)d_in[2];
    const float* bias  = (const float*)d_in[3];
    const float* BB    = (const float*)d_in[4];
    const float* GG    = (const float*)d_in[5];
    const int*   Pi    = (const int*)d_in[6];   // int32 (JAX x64 disabled)
    float* y = (float*)d_out;
    const int ntheta = in_sizes[1];             // 2048 -> rows 0,1 only

    float* u = nullptr;
    cudaGetSymbolAddress((void**)&u, g_u);

    cudaFuncSetAttribute(k_gemm, cudaFuncAttributeMaxDynamicSharedMemorySize,
                         NSTAGE * STAGE);

    // Fastfood weight construction (pass-1 FWHT collapsed analytically)
    k_ab<<<2, 256>>>(theta, BB, ntheta);
    k_gather_rows<<<1024, 256>>>(Pi, GG);
    k_reduce2<<<1, 256>>>();
    k_fwht_cols4<<<256, 256>>>(u);

    // Split-bf16 operand prep
    k_split_x<<<(MTOT * INF / 4 + 255) / 256, 256>>>(x);
    k_build_B<<<(DD / 4 + 255) / 256, 256>>>(W0);

    // Tensor-core GEMM + bias
    dim3 grid(OUTF / BN, MTOT / BM);
    k_gemm<<<grid, 256, NSTAGE * STAGE>>>(bias, y);
}